// round 5
// baseline (speedup 1.0000x reference)
#include <cuda_runtime.h>
#include <math.h>
#include <stdint.h>

#define NN      50000
#define NE      800000
#define NG      500
#define DIM     64
#define HID     256
#define NCLS    2000
#define NAT     100
#define TABLE_N 8193
#define CUTOFF  5.0f

#define FLAG_BETA  1
#define FLAG_RELUA 2

// ---------------- scratch (device globals; no allocation allowed) ----------
__device__ float g_node[NN * DIM];
__device__ float g_newnode[NN * DIM];   // also reused as t-buffer
__device__ float g_agg[NN * DIM];
__device__ float g_atom[NN * HID];
__device__ float g_res[NN * HID];
__device__ float g_table[3 * TABLE_N * DIM];
__device__ float g_gsum[NG * HID];
__device__ float g_gcnt[NG];
__device__ float g_gmean[NG * HID];

// ---------------- activations ---------------------------------------------
__device__ __forceinline__ float softplusf(float x) {
    return fmaxf(x, 0.0f) + log1pf(expf(-fabsf(x)));
}
__device__ __forceinline__ float sp2f(float x) {       // 2*softplus(0.5x)
    return 2.0f * softplusf(0.5f * x);
}
__device__ __forceinline__ float sspf(float x) {       // softplus(x) - ln2
    return softplusf(x) - 0.69314718055994531f;
}

// ---------------- f32x2 packed math ----------------------------------------
__device__ __forceinline__ uint64_t pack2(float lo, float hi) {
    uint64_t r;
    asm("mov.b64 %0, {%1, %2};" : "=l"(r) : "f"(lo), "f"(hi));
    return r;
}
__device__ __forceinline__ uint64_t dup2(float v) {
    uint64_t r;
    asm("mov.b64 %0, {%1, %1};" : "=l"(r) : "f"(v));
    return r;
}
__device__ __forceinline__ void ffma2(uint64_t& d, uint64_t a, uint64_t b) {
    asm("fma.rn.f32x2 %0, %1, %2, %0;" : "+l"(d) : "l"(a), "l"(b));
}
__device__ __forceinline__ void unpack2(uint64_t v, float& lo, float& hi) {
    asm("mov.b64 {%0, %1}, %2;" : "=f"(lo), "=f"(hi) : "l"(v));
}

// ---------------- tiny utility kernels -------------------------------------
__global__ void zero_kernel(float* __restrict__ p, int n) {
    int i = blockIdx.x * blockDim.x + threadIdx.x;
    if (i < n) p[i] = 0.0f;
}

__global__ void embed_kernel(const int* __restrict__ types,
                             const float* __restrict__ emb,
                             float* __restrict__ node) {
    int i = blockIdx.x * blockDim.x + threadIdx.x;
    if (i >= NN * DIM) return;
    int n = i >> 6;      // /64
    int c = i & 63;
    node[i] = emb[types[n] * DIM + c];
}

// eh(d) table per layer: sp2(sp2(rbf(d)@cf1 + b1)@cf2 + b2)
__global__ void build_table_kernel(const float* __restrict__ cf1_w,  // [3,5,64]
                                   const float* __restrict__ cf1_b,  // [3,64]
                                   const float* __restrict__ cf2_w,  // [3,64,64]
                                   const float* __restrict__ cf2_b,  // [3,64]
                                   float* __restrict__ table) {
    __shared__ float h[DIM];
    int b = blockIdx.x;
    int layer = b / TABLE_N;
    int ent   = b % TABLE_N;
    int j = threadIdx.x;

    const float gap = CUTOFF / 4.0f;                 // linspace(0,5,5) gap = 1.25
    float d = (float)ent * (CUTOFF / (float)(TABLE_N - 1));

    float rbf[5];
#pragma unroll
    for (int r = 0; r < 5; r++) {
        float t = d - (float)r * gap;
        rbf[r] = expf(-(1.0f / gap) * t * t);
    }
    float acc = cf1_b[layer * DIM + j];
#pragma unroll
    for (int r = 0; r < 5; r++)
        acc += rbf[r] * cf1_w[(layer * 5 + r) * DIM + j];
    h[j] = sp2f(acc);
    __syncthreads();

    float acc2 = cf2_b[layer * DIM + j];
    const float* W = cf2_w + layer * DIM * DIM;
#pragma unroll 8
    for (int k = 0; k < DIM; k++)
        acc2 += h[k] * W[k * DIM + j];
    table[(layer * TABLE_N + ent) * DIM + j] = sp2f(acc2);
}

// 16 lanes per edge; each lane handles 4 consecutive floats (float4, 128-bit)
__global__ void edge_kernel(const int* __restrict__ src,
                            const int* __restrict__ dst,
                            const float* __restrict__ dist,
                            const float* __restrict__ newnode,
                            const float* __restrict__ table,   // [TABLE_N,64]
                            float* __restrict__ agg) {
    int idx = blockIdx.x * blockDim.x + threadIdx.x;
    int e = idx >> 4;
    if (e >= NE) return;
    int lane = idx & 15;

    int s = __ldg(src + e);
    int t = __ldg(dst + e);
    float dd = __ldg(dist + e);

    float f = dd * ((float)(TABLE_N - 1) / CUTOFF);
    f = fminf(fmaxf(f, 0.0f), (float)(TABLE_N - 1));
    int i0 = (int)f;
    if (i0 > TABLE_N - 2) i0 = TABLE_N - 2;
    float fr = f - (float)i0;

    const float4* nn = (const float4*)(newnode + (size_t)s * DIM);
    const float4* tb = (const float4*)(table + (size_t)i0 * DIM);

    float4 a  = nn[lane];
    float4 u0 = tb[lane];          // row i0
    float4 u1 = tb[lane + 16];     // row i0+1 (adjacent, +64 floats)

    float m0 = a.x * fmaf(fr, u1.x - u0.x, u0.x);
    float m1 = a.y * fmaf(fr, u1.y - u0.y, u0.y);
    float m2 = a.z * fmaf(fr, u1.z - u0.z, u0.z);
    float m3 = a.w * fmaf(fr, u1.w - u0.w, u0.w);

    float* out = agg + (size_t)t * DIM + lane * 4;
    asm volatile("red.global.add.v4.f32 [%0], {%1, %2, %3, %4};"
                 :: "l"(out), "f"(m0), "f"(m1), "f"(m2), "f"(m3) : "memory");
}

// graph pooling: accumulate res rows into per-graph sums (float4 lanes)
__global__ void pool_kernel(const int* __restrict__ gid,
                            const float* __restrict__ res,
                            float* __restrict__ gsum) {
    int idx = blockIdx.x * blockDim.x + threadIdx.x;   // NN * 64 threads
    if (idx >= NN * (HID / 4)) return;
    int n  = idx >> 6;        // /64
    int c4 = idx & 63;
    int g = __ldg(gid + n);
    const float4 v = ((const float4*)(res + (size_t)n * HID))[c4];
    float* out = gsum + (size_t)g * HID + c4 * 4;
    asm volatile("red.global.add.v4.f32 [%0], {%1, %2, %3, %4};"
                 :: "l"(out), "f"(v.x), "f"(v.y), "f"(v.z), "f"(v.w) : "memory");
}

__global__ void count_kernel(const int* __restrict__ gid, float* __restrict__ gcnt) {
    int i = blockIdx.x * blockDim.x + threadIdx.x;
    if (i < NN) atomicAdd(&gcnt[gid[i]], 1.0f);
}

__global__ void mean_kernel(const float* __restrict__ gsum,
                            const float* __restrict__ gcnt,
                            float* __restrict__ gmean) {
    int i = blockIdx.x * blockDim.x + threadIdx.x;
    if (i >= NG * HID) return;
    int g = i >> 8;   // /256
    gmean[i] = gsum[i] / fmaxf(gcnt[g], 1.0f);
}

// ---------------- SGEMM: f32x2, dup-B smem, KC=32, double-buffered ----------
// C = act(A@B + bias) [+C].  A:[M,K] rm, B:[K,N] rm.  K % 32 == 0.
// BM=128, BN=64, KC=32, 256 threads.
#define BM 128
#define BN 64
#define KC 32

__global__ __launch_bounds__(256)
void sgemm_kernel(const float* __restrict__ A,
                  const float* __restrict__ B,
                  const float* __restrict__ bias,
                  float* __restrict__ C,
                  int M, int N, int K, int act, int flags) {
    __shared__ float As[2][KC][BM];        // 2 x 16 KB
    __shared__ float Bd[2][KC][BN * 2];    // 2 x 16 KB, duplicated pairs

    int bm = blockIdx.y * BM;
    int bn = blockIdx.x * BN;
    int tid = threadIdx.x;
    int tr = tid >> 3;             // 0..31
    int tc = tid & 7;              // 0..7
    int row0 = tr * 4;

    // A-load mapping (per thread): 4 float4 slots
    int a_m[4], a_ks[4];
#pragma unroll
    for (int q = 0; q < 4; q++) {
        int lin = tid * 4 + q;
        a_m[q]  = lin >> 3;
        a_ks[q] = (lin & 7) * 4;
    }
    // B-load mapping: row kk = tid>>3, cols n0..n0+7
    int b_kk = tid >> 3;
    int b_n0 = (tid & 7) * 8;

    const bool reluA = (flags & FLAG_RELUA) != 0;
    int nc = K / KC;

    uint64_t acc[2][8];
#pragma unroll
    for (int i = 0; i < 2; i++)
#pragma unroll
        for (int j = 0; j < 8; j++) acc[i][j] = 0ull;

    // ---- prologue: load chunk 0 into buffer 0 ----
    {
#pragma unroll
        for (int q = 0; q < 4; q++) {
            int gr = bm + a_m[q];
            float4 v = make_float4(0.f, 0.f, 0.f, 0.f);
            if (gr < M) v = *(const float4*)(A + (size_t)gr * K + a_ks[q]);
            if (reluA) {
                v.x = fmaxf(v.x, 0.f); v.y = fmaxf(v.y, 0.f);
                v.z = fmaxf(v.z, 0.f); v.w = fmaxf(v.w, 0.f);
            }
            As[0][a_ks[q] + 0][a_m[q]] = v.x;
            As[0][a_ks[q] + 1][a_m[q]] = v.y;
            As[0][a_ks[q] + 2][a_m[q]] = v.z;
            As[0][a_ks[q] + 3][a_m[q]] = v.w;
        }
        const float* Brow = B + (size_t)b_kk * N + bn;
#pragma unroll
        for (int p = 0; p < 4; p++) {
            int n = b_n0 + p * 2;
            float x = 0.f, y = 0.f;
            int gc = bn + n;
            if (gc + 1 < N) { float2 v2 = *(const float2*)(Brow + n); x = v2.x; y = v2.y; }
            else if (gc < N) x = Brow[n];
            *(uint64_t*)&Bd[0][b_kk][2 * n]     = dup2(x);
            *(uint64_t*)&Bd[0][b_kk][2 * n + 2] = dup2(y);
        }
    }
    __syncthreads();

    for (int c = 0; c < nc; c++) {
        int cur = c & 1, nxt = cur ^ 1;
        int k0n = (c + 1) * KC;

        // prefetch next chunk into registers
        float4 pa[4];
        float  pbx[4], pby[4];
        if (c + 1 < nc) {
#pragma unroll
            for (int q = 0; q < 4; q++) {
                int gr = bm + a_m[q];
                float4 v = make_float4(0.f, 0.f, 0.f, 0.f);
                if (gr < M) v = *(const float4*)(A + (size_t)gr * K + k0n + a_ks[q]);
                if (reluA) {
                    v.x = fmaxf(v.x, 0.f); v.y = fmaxf(v.y, 0.f);
                    v.z = fmaxf(v.z, 0.f); v.w = fmaxf(v.w, 0.f);
                }
                pa[q] = v;
            }
            const float* Brow = B + (size_t)(k0n + b_kk) * N + bn;
#pragma unroll
            for (int p = 0; p < 4; p++) {
                int n = b_n0 + p * 2;
                float x = 0.f, y = 0.f;
                int gc = bn + n;
                if (gc + 1 < N) { float2 v2 = *(const float2*)(Brow + n); x = v2.x; y = v2.y; }
                else if (gc < N) x = Brow[n];
                pbx[p] = x; pby[p] = y;
            }
        }

        // compute current chunk
#pragma unroll
        for (int kk = 0; kk < KC; kk++) {
            float4 av = *(const float4*)&As[cur][kk][row0];
            uint64_t ap0 = pack2(av.x, av.y);
            uint64_t ap1 = pack2(av.z, av.w);
            uint64_t b[8];
#pragma unroll
            for (int j = 0; j < 4; j++) {
                float4 bv = *(const float4*)&Bd[cur][kk][j * 32 + tc * 4];
                b[j * 2]     = pack2(bv.x, bv.y);
                b[j * 2 + 1] = pack2(bv.z, bv.w);
            }
#pragma unroll
            for (int cc = 0; cc < 8; cc++) {
                ffma2(acc[0][cc], ap0, b[cc]);
                ffma2(acc[1][cc], ap1, b[cc]);
            }
        }

        // store prefetched chunk into the other buffer
        if (c + 1 < nc) {
#pragma unroll
            for (int q = 0; q < 4; q++) {
                As[nxt][a_ks[q] + 0][a_m[q]] = pa[q].x;
                As[nxt][a_ks[q] + 1][a_m[q]] = pa[q].y;
                As[nxt][a_ks[q] + 2][a_m[q]] = pa[q].z;
                As[nxt][a_ks[q] + 3][a_m[q]] = pa[q].w;
            }
#pragma unroll
            for (int p = 0; p < 4; p++) {
                int n = b_n0 + p * 2;
                *(uint64_t*)&Bd[nxt][b_kk][2 * n]     = dup2(pbx[p]);
                *(uint64_t*)&Bd[nxt][b_kk][2 * n + 2] = dup2(pby[p]);
            }
        }
        __syncthreads();
    }

    // ---- epilogue ----
#pragma unroll
    for (int rp = 0; rp < 2; rp++) {
#pragma unroll
        for (int h = 0; h < 2; h++) {
            int r = bm + row0 + rp * 2 + h;
            if (r >= M) continue;
            float vals[8];
#pragma unroll
            for (int cc = 0; cc < 8; cc++) {
                float lo, hi;
                unpack2(acc[rp][cc], lo, hi);
                vals[cc] = h ? hi : lo;
            }
#pragma unroll
            for (int j = 0; j < 4; j++) {
                int c0 = bn + j * 16 + tc * 2;
#pragma unroll
                for (int u = 0; u < 2; u++) {
                    int cidx = c0 + u;
                    if (cidx >= N) continue;
                    float v = vals[j * 2 + u];
                    if (bias) v += bias[cidx];
                    if (act == 1) v = sp2f(v);
                    else if (act == 2) v = sspf(v);
                    if (flags & FLAG_BETA) v += C[(size_t)r * N + cidx];
                    C[(size_t)r * N + cidx] = v;
                }
            }
        }
    }
}

// ---------------- driver ----------------------------------------------------
static inline dim3 gemm_grid(int M, int N) {
    return dim3((N + BN - 1) / BN, (M + BM - 1) / BM);
}

extern "C" void kernel_launch(void* const* d_in, const int* in_sizes, int n_in,
                              void* d_out, int out_size) {
    const int*   node_types = (const int*)  d_in[0];
    const int*   edge_src   = (const int*)  d_in[1];
    const int*   edge_dst   = (const int*)  d_in[2];
    const int*   graph_ids  = (const int*)  d_in[3];
    const float* distance   = (const float*)d_in[4];
    const float* emb        = (const float*)d_in[5];
    const float* conv_w1    = (const float*)d_in[6];
    const float* cf1_w      = (const float*)d_in[7];
    const float* cf1_b      = (const float*)d_in[8];
    const float* cf2_w      = (const float*)d_in[9];
    const float* cf2_b      = (const float*)d_in[10];
    const float* nl2_w      = (const float*)d_in[11];
    const float* nl2_b      = (const float*)d_in[12];
    const float* nl3_w      = (const float*)d_in[13];
    const float* nl3_b      = (const float*)d_in[14];
    const float* d1_w       = (const float*)d_in[15];
    const float* d1_b       = (const float*)d_in[16];
    const float* d2_w       = (const float*)d_in[17];
    const float* d2_b       = (const float*)d_in[18];
    const float* cls_w      = (const float*)d_in[19];
    const float* cls_b      = (const float*)d_in[20];
    const float* ac_w       = (const float*)d_in[21];
    const float* ac_b       = (const float*)d_in[22];
    float* out = (float*)d_out;

    float *node, *newnode, *agg, *atom, *res, *table, *gsum, *gcnt, *gmean;
    cudaGetSymbolAddress((void**)&node,    g_node);
    cudaGetSymbolAddress((void**)&newnode, g_newnode);
    cudaGetSymbolAddress((void**)&agg,     g_agg);
    cudaGetSymbolAddress((void**)&atom,    g_atom);
    cudaGetSymbolAddress((void**)&res,     g_res);
    cudaGetSymbolAddress((void**)&table,   g_table);
    cudaGetSymbolAddress((void**)&gsum,    g_gsum);
    cudaGetSymbolAddress((void**)&gcnt,    g_gcnt);
    cudaGetSymbolAddress((void**)&gmean,   g_gmean);

    // node = emb[node_types]
    embed_kernel<<<(NN * DIM + 255) / 256, 256>>>(node_types, emb, node);

    // per-layer eh(d) lookup tables
    build_table_kernel<<<3 * TABLE_N, DIM>>>(cf1_w, cf1_b, cf2_w, cf2_b, table);

    dim3 g64 = gemm_grid(NN, DIM);
    for (int l = 0; l < 3; l++) {
        // newnode = node @ w1
        sgemm_kernel<<<g64, 256>>>(node, conv_w1 + (size_t)l * DIM * DIM,
                                   nullptr, newnode, NN, DIM, DIM, 0, 0);
        // agg = 0
        zero_kernel<<<(NN * DIM + 255) / 256, 256>>>(agg, NN * DIM);
        // agg[dst] += newnode[src] * eh(d)
        edge_kernel<<<(NE * 16 + 255) / 256, 256>>>(
            edge_src, edge_dst, distance, newnode,
            table + (size_t)l * TABLE_N * DIM, agg);
        // t = sp2(agg @ nl2 + b2)   (reuse newnode as t)
        sgemm_kernel<<<g64, 256>>>(agg, nl2_w + (size_t)l * DIM * DIM,
                                   nl2_b + l * DIM, newnode, NN, DIM, DIM, 1, 0);
        // node += t @ nl3 + b3
        sgemm_kernel<<<g64, 256>>>(newnode, nl3_w + (size_t)l * DIM * DIM,
                                   nl3_b + l * DIM, node, NN, DIM, DIM, 0, FLAG_BETA);
    }

    // atom = ssp(node @ d1 + b)
    sgemm_kernel<<<gemm_grid(NN, HID), 256>>>(node, d1_w, d1_b, atom,
                                              NN, HID, DIM, 2, 0);
    // res = atom @ d2 + b
    sgemm_kernel<<<gemm_grid(NN, HID), 256>>>(atom, d2_w, d2_b, res,
                                              NN, HID, HID, 0, 0);
    // atoms_preds = relu(res) @ ac + b   -> out[0 : NN*100]
    sgemm_kernel<<<gemm_grid(NN, NAT), 256>>>(res, ac_w, ac_b, out,
                                              NN, NAT, HID, 0, FLAG_RELUA);

    // graph pooling
    zero_kernel<<<(NG * HID + 255) / 256, 256>>>(gsum, NG * HID);
    zero_kernel<<<(NG + 255) / 256, 256>>>(gcnt, NG);
    pool_kernel<<<(NN * (HID / 4) + 255) / 256, 256>>>(graph_ids, res, gsum);
    count_kernel<<<(NN + 255) / 256, 256>>>(graph_ids, gcnt);
    mean_kernel<<<(NG * HID + 255) / 256, 256>>>(gsum, gcnt, gmean);

    // cls_preds = gmean @ cls_w + b -> out[NN*100 : ]
    sgemm_kernel<<<gemm_grid(NG, NCLS), 256>>>(gmean, cls_w, cls_b,
                                               out + (size_t)NN * NAT,
                                               NG, NCLS, HID, 0, 0);
}

// round 7
// speedup vs baseline: 1.5185x; 1.5185x over previous
#include <cuda_runtime.h>
#include <math.h>
#include <stdint.h>

#define NN      50000
#define NE      800000
#define NG      500
#define DIM     64
#define HID     256
#define NCLS    2000
#define NAT     100
#define TABLE_N 8193
#define CUTOFF  5.0f

#define FLAG_BETA  1
#define FLAG_RELUA 2

// ---------------- scratch (device globals; no allocation allowed) ----------
__device__ float g_node[NN * DIM];
__device__ float g_newnode[NN * DIM];   // also reused as t-buffer
__device__ float g_agg[NN * DIM];
__device__ float g_atom[NN * HID];
__device__ float g_res[NN * HID];
__device__ float g_table[3 * TABLE_N * DIM];
__device__ float g_gsum[NG * HID];
__device__ float g_gcnt[NG];
__device__ float g_gmean[NG * HID];

// ---------------- activations ---------------------------------------------
__device__ __forceinline__ float softplusf(float x) {
    return fmaxf(x, 0.0f) + log1pf(expf(-fabsf(x)));
}
__device__ __forceinline__ float sp2f(float x) {       // 2*softplus(0.5x)
    return 2.0f * softplusf(0.5f * x);
}
__device__ __forceinline__ float sspf(float x) {       // softplus(x) - ln2
    return softplusf(x) - 0.69314718055994531f;
}

// ---------------- f32x2 packed math ----------------------------------------
__device__ __forceinline__ uint64_t pack2(float lo, float hi) {
    uint64_t r;
    asm("mov.b64 %0, {%1, %2};" : "=l"(r) : "f"(lo), "f"(hi));
    return r;
}
__device__ __forceinline__ uint64_t dup2(float v) {
    uint64_t r;
    asm("mov.b64 %0, {%1, %1};" : "=l"(r) : "f"(v));
    return r;
}
__device__ __forceinline__ void ffma2(uint64_t& d, uint64_t a, uint64_t b) {
    asm("fma.rn.f32x2 %0, %1, %2, %0;" : "+l"(d) : "l"(a), "l"(b));
}
__device__ __forceinline__ void unpack2(uint64_t v, float& lo, float& hi) {
    asm("mov.b64 {%0, %1}, %2;" : "=f"(lo), "=f"(hi) : "l"(v));
}

// ---------------- tiny utility kernels -------------------------------------
__global__ void zero_kernel(float* __restrict__ p, int n) {
    int i = blockIdx.x * blockDim.x + threadIdx.x;
    if (i < n) p[i] = 0.0f;
}

__global__ void embed_kernel(const int* __restrict__ types,
                             const float* __restrict__ emb,
                             float* __restrict__ node) {
    int i = blockIdx.x * blockDim.x + threadIdx.x;
    if (i >= NN * DIM) return;
    int n = i >> 6;      // /64
    int c = i & 63;
    node[i] = emb[types[n] * DIM + c];
}

// eh(d) table per layer: sp2(sp2(rbf(d)@cf1 + b1)@cf2 + b2)
__global__ void build_table_kernel(const float* __restrict__ cf1_w,  // [3,5,64]
                                   const float* __restrict__ cf1_b,  // [3,64]
                                   const float* __restrict__ cf2_w,  // [3,64,64]
                                   const float* __restrict__ cf2_b,  // [3,64]
                                   float* __restrict__ table) {
    __shared__ float h[DIM];
    int b = blockIdx.x;
    int layer = b / TABLE_N;
    int ent   = b % TABLE_N;
    int j = threadIdx.x;

    const float gap = CUTOFF / 4.0f;                 // linspace(0,5,5) gap = 1.25
    float d = (float)ent * (CUTOFF / (float)(TABLE_N - 1));

    float rbf[5];
#pragma unroll
    for (int r = 0; r < 5; r++) {
        float t = d - (float)r * gap;
        rbf[r] = expf(-(1.0f / gap) * t * t);
    }
    float acc = cf1_b[layer * DIM + j];
#pragma unroll
    for (int r = 0; r < 5; r++)
        acc += rbf[r] * cf1_w[(layer * 5 + r) * DIM + j];
    h[j] = sp2f(acc);
    __syncthreads();

    float acc2 = cf2_b[layer * DIM + j];
    const float* W = cf2_w + layer * DIM * DIM;
#pragma unroll 8
    for (int k = 0; k < DIM; k++)
        acc2 += h[k] * W[k * DIM + j];
    table[(layer * TABLE_N + ent) * DIM + j] = sp2f(acc2);
}

// 16 lanes per edge; each lane handles 4 consecutive floats (float4, 128-bit)
__global__ void edge_kernel(const int* __restrict__ src,
                            const int* __restrict__ dst,
                            const float* __restrict__ dist,
                            const float* __restrict__ newnode,
                            const float* __restrict__ table,   // [TABLE_N,64]
                            float* __restrict__ agg) {
    int idx = blockIdx.x * blockDim.x + threadIdx.x;
    int e = idx >> 4;
    if (e >= NE) return;
    int lane = idx & 15;

    int s = __ldg(src + e);
    int t = __ldg(dst + e);
    float dd = __ldg(dist + e);

    float f = dd * ((float)(TABLE_N - 1) / CUTOFF);
    f = fminf(fmaxf(f, 0.0f), (float)(TABLE_N - 1));
    int i0 = (int)f;
    if (i0 > TABLE_N - 2) i0 = TABLE_N - 2;
    float fr = f - (float)i0;

    const float4* nn = (const float4*)(newnode + (size_t)s * DIM);
    const float4* tb = (const float4*)(table + (size_t)i0 * DIM);

    float4 a  = nn[lane];
    float4 u0 = tb[lane];          // row i0
    float4 u1 = tb[lane + 16];     // row i0+1 (adjacent, +64 floats)

    float m0 = a.x * fmaf(fr, u1.x - u0.x, u0.x);
    float m1 = a.y * fmaf(fr, u1.y - u0.y, u0.y);
    float m2 = a.z * fmaf(fr, u1.z - u0.z, u0.z);
    float m3 = a.w * fmaf(fr, u1.w - u0.w, u0.w);

    float* out = agg + (size_t)t * DIM + lane * 4;
    asm volatile("red.global.add.v4.f32 [%0], {%1, %2, %3, %4};"
                 :: "l"(out), "f"(m0), "f"(m1), "f"(m2), "f"(m3) : "memory");
}

// graph pooling: accumulate res rows into per-graph sums
__global__ void pool_kernel(const int* __restrict__ gid,
                            const float* __restrict__ res,
                            float* __restrict__ gsum) {
    int idx = blockIdx.x * blockDim.x + threadIdx.x;   // NN * 128 threads
    if (idx >= NN * (HID / 2)) return;
    int n  = idx >> 7;        // /128
    int c2 = idx & 127;
    int g = __ldg(gid + n);
    const float2 v = ((const float2*)(res + (size_t)n * HID))[c2];
    float* out = gsum + (size_t)g * HID + c2 * 2;
    asm volatile("red.global.add.v2.f32 [%0], {%1, %2};"
                 :: "l"(out), "f"(v.x), "f"(v.y) : "memory");
}

__global__ void count_kernel(const int* __restrict__ gid, float* __restrict__ gcnt) {
    int i = blockIdx.x * blockDim.x + threadIdx.x;
    if (i < NN) atomicAdd(&gcnt[gid[i]], 1.0f);
}

__global__ void mean_kernel(const float* __restrict__ gsum,
                            const float* __restrict__ gcnt,
                            float* __restrict__ gmean) {
    int i = blockIdx.x * blockDim.x + threadIdx.x;
    if (i >= NG * HID) return;
    int g = i >> 8;   // /256
    gmean[i] = gsum[i] / fmaxf(gcnt[g], 1.0f);
}

// ---------------- SGEMM: f32x2, dup-B smem, KC=32 chunks (R3 version) -------
// C = act(A@B + bias) [+C].  A:[M,K] rm, B:[K,N] rm.
#define BM 128
#define BN 64
#define KC 32

__global__ __launch_bounds__(256)
void sgemm_kernel(const float* __restrict__ A,
                  const float* __restrict__ B,
                  const float* __restrict__ bias,
                  float* __restrict__ C,
                  int M, int N, int K, int act, int flags) {
    __shared__ float As[KC][BM];        // 16 KB, k-major
    __shared__ float Bd[KC][BN * 2];    // 16 KB, duplicated: Bd[k][2n]=Bd[k][2n+1]=B[k][n]

    int bm = blockIdx.y * BM;
    int bn = blockIdx.x * BN;
    int tid = threadIdx.x;
    int tr = tid >> 3;             // 0..31
    int tc = tid & 7;              // 0..7
    int row0 = tr * 4;

    uint64_t acc[2][8];            // [row-pair][col]
#pragma unroll
    for (int i = 0; i < 2; i++)
#pragma unroll
        for (int j = 0; j < 8; j++) acc[i][j] = 0ull;

    const bool reluA = (flags & FLAG_RELUA) != 0;

    for (int k0 = 0; k0 < K; k0 += KC) {
        // ---- load A chunk (BM x KC = 4096 floats): 4 float4 per thread ----
#pragma unroll
        for (int q = 0; q < 4; q++) {
            int lin = tid * 4 + q;          // 0..1023 float4 slots
            int m   = lin >> 3;             // 0..127
            int ks  = (lin & 7) * 4;        // 0,4,...,28
            int gr  = bm + m;
            float4 v = make_float4(0.f, 0.f, 0.f, 0.f);
            if (gr < M)
                v = *(const float4*)(A + (size_t)gr * K + k0 + ks);
            if (reluA) {
                v.x = fmaxf(v.x, 0.f); v.y = fmaxf(v.y, 0.f);
                v.z = fmaxf(v.z, 0.f); v.w = fmaxf(v.w, 0.f);
            }
            As[ks + 0][m] = v.x;
            As[ks + 1][m] = v.y;
            As[ks + 2][m] = v.z;
            As[ks + 3][m] = v.w;
        }
        // ---- load B chunk duplicated (KC x BN src): 8 floats per thread ----
        {
            int kk = tid >> 3;              // 0..31
            int n0 = (tid & 7) * 8;         // 0,8,...,56
            const float* Brow = B + (size_t)(k0 + kk) * N + bn;
#pragma unroll
            for (int p = 0; p < 4; p++) {
                int n = n0 + p * 2;
                float x = 0.f, y = 0.f;
                int gc = bn + n;
                if (gc + 1 < N) {
                    float2 v2 = *(const float2*)(Brow + n);
                    x = v2.x; y = v2.y;
                } else {
                    if (gc < N) x = Brow[n];
                }
                *(uint64_t*)&Bd[kk][2 * n]     = dup2(x);
                *(uint64_t*)&Bd[kk][2 * n + 2] = dup2(y);
            }
        }
        __syncthreads();

#pragma unroll
        for (int kk = 0; kk < KC; kk++) {
            float4 av = *(const float4*)&As[kk][row0];
            uint64_t ap0 = pack2(av.x, av.y);     // rows (row0, row0+1)
            uint64_t ap1 = pack2(av.z, av.w);     // rows (row0+2, row0+3)
            uint64_t b[8];
#pragma unroll
            for (int j = 0; j < 4; j++) {
                float4 bv = *(const float4*)&Bd[kk][j * 32 + tc * 4];
                b[j * 2]     = pack2(bv.x, bv.y);
                b[j * 2 + 1] = pack2(bv.z, bv.w);
            }
#pragma unroll
            for (int c = 0; c < 8; c++) {
                ffma2(acc[0][c], ap0, b[c]);
                ffma2(acc[1][c], ap1, b[c]);
            }
        }
        __syncthreads();
    }

    // ---- epilogue: 4 rows x 8 cols ----
#pragma unroll
    for (int rp = 0; rp < 2; rp++) {
#pragma unroll
        for (int h = 0; h < 2; h++) {
            int r = bm + row0 + rp * 2 + h;
            if (r >= M) continue;
            float vals[8];
#pragma unroll
            for (int c = 0; c < 8; c++) {
                float lo, hi;
                unpack2(acc[rp][c], lo, hi);
                vals[c] = h ? hi : lo;
            }
#pragma unroll
            for (int j = 0; j < 4; j++) {
                int c0 = bn + j * 16 + tc * 2;
#pragma unroll
                for (int u = 0; u < 2; u++) {
                    int c = c0 + u;
                    if (c >= N) continue;
                    float v = vals[j * 2 + u];
                    if (bias) v += bias[c];
                    if (act == 1) v = sp2f(v);
                    else if (act == 2) v = sspf(v);
                    if (flags & FLAG_BETA) v += C[(size_t)r * N + c];
                    C[(size_t)r * N + c] = v;
                }
            }
        }
    }
}

// ---------------- driver ----------------------------------------------------
static inline dim3 gemm_grid(int M, int N) {
    return dim3((N + BN - 1) / BN, (M + BM - 1) / BM);
}

extern "C" void kernel_launch(void* const* d_in, const int* in_sizes, int n_in,
                              void* d_out, int out_size) {
    const int*   node_types = (const int*)  d_in[0];
    const int*   edge_src   = (const int*)  d_in[1];
    const int*   edge_dst   = (const int*)  d_in[2];
    const int*   graph_ids  = (const int*)  d_in[3];
    const float* distance   = (const float*)d_in[4];
    const float* emb        = (const float*)d_in[5];
    const float* conv_w1    = (const float*)d_in[6];
    const float* cf1_w      = (const float*)d_in[7];
    const float* cf1_b      = (const float*)d_in[8];
    const float* cf2_w      = (const float*)d_in[9];
    const float* cf2_b      = (const float*)d_in[10];
    const float* nl2_w      = (const float*)d_in[11];
    const float* nl2_b      = (const float*)d_in[12];
    const float* nl3_w      = (const float*)d_in[13];
    const float* nl3_b      = (const float*)d_in[14];
    const float* d1_w       = (const float*)d_in[15];
    const float* d1_b       = (const float*)d_in[16];
    const float* d2_w       = (const float*)d_in[17];
    const float* d2_b       = (const float*)d_in[18];
    const float* cls_w      = (const float*)d_in[19];
    const float* cls_b      = (const float*)d_in[20];
    const float* ac_w       = (const float*)d_in[21];
    const float* ac_b       = (const float*)d_in[22];
    float* out = (float*)d_out;

    float *node, *newnode, *agg, *atom, *res, *table, *gsum, *gcnt, *gmean;
    cudaGetSymbolAddress((void**)&node,    g_node);
    cudaGetSymbolAddress((void**)&newnode, g_newnode);
    cudaGetSymbolAddress((void**)&agg,     g_agg);
    cudaGetSymbolAddress((void**)&atom,    g_atom);
    cudaGetSymbolAddress((void**)&res,     g_res);
    cudaGetSymbolAddress((void**)&table,   g_table);
    cudaGetSymbolAddress((void**)&gsum,    g_gsum);
    cudaGetSymbolAddress((void**)&gcnt,    g_gcnt);
    cudaGetSymbolAddress((void**)&gmean,   g_gmean);

    // node = emb[node_types]
    embed_kernel<<<(NN * DIM + 255) / 256, 256>>>(node_types, emb, node);

    // per-layer eh(d) lookup tables
    build_table_kernel<<<3 * TABLE_N, DIM>>>(cf1_w, cf1_b, cf2_w, cf2_b, table);

    dim3 g64 = gemm_grid(NN, DIM);
    for (int l = 0; l < 3; l++) {
        // newnode = node @ w1
        sgemm_kernel<<<g64, 256>>>(node, conv_w1 + (size_t)l * DIM * DIM,
                                   nullptr, newnode, NN, DIM, DIM, 0, 0);
        // agg = 0
        zero_kernel<<<(NN * DIM + 255) / 256, 256>>>(agg, NN * DIM);
        // agg[dst] += newnode[src] * eh(d)
        edge_kernel<<<(NE * 16 + 255) / 256, 256>>>(
            edge_src, edge_dst, distance, newnode,
            table + (size_t)l * TABLE_N * DIM, agg);
        // t = sp2(agg @ nl2 + b2)   (reuse newnode as t)
        sgemm_kernel<<<g64, 256>>>(agg, nl2_w + (size_t)l * DIM * DIM,
                                   nl2_b + l * DIM, newnode, NN, DIM, DIM, 1, 0);
        // node += t @ nl3 + b3
        sgemm_kernel<<<g64, 256>>>(newnode, nl3_w + (size_t)l * DIM * DIM,
                                   nl3_b + l * DIM, node, NN, DIM, DIM, 0, FLAG_BETA);
    }

    // atom = ssp(node @ d1 + b)
    sgemm_kernel<<<gemm_grid(NN, HID), 256>>>(node, d1_w, d1_b, atom,
                                              NN, HID, DIM, 2, 0);
    // res = atom @ d2 + b
    sgemm_kernel<<<gemm_grid(NN, HID), 256>>>(atom, d2_w, d2_b, res,
                                              NN, HID, HID, 0, 0);
    // atoms_preds = relu(res) @ ac + b   -> out[0 : NN*100]
    sgemm_kernel<<<gemm_grid(NN, NAT), 256>>>(res, ac_w, ac_b, out,
                                              NN, NAT, HID, 0, FLAG_RELUA);

    // graph pooling
    zero_kernel<<<(NG * HID + 255) / 256, 256>>>(gsum, NG * HID);
    zero_kernel<<<(NG + 255) / 256, 256>>>(gcnt, NG);
    pool_kernel<<<(NN * (HID / 2) + 255) / 256, 256>>>(graph_ids, res, gsum);
    count_kernel<<<(NN + 255) / 256, 256>>>(graph_ids, gcnt);
    mean_kernel<<<(NG * HID + 255) / 256, 256>>>(gsum, gcnt, gmean);

    // cls_preds = gmean @ cls_w + b -> out[NN*100 : ]
    sgemm_kernel<<<gemm_grid(NG, NCLS), 256>>>(gmean, cls_w, cls_b,
                                               out + (size_t)NN * NAT,
                                               NG, NCLS, HID, 0, 0);
}

// round 9
// speedup vs baseline: 1.5836x; 1.0429x over previous
#include <cuda_runtime.h>
#include <math.h>
#include <stdint.h>

#define NN      50000
#define NE      800000
#define NG      500
#define DIM     64
#define HID     256
#define NCLS    2000
#define NAT     100
#define TABLE_N 8193
#define CUTOFF  5.0f

#define FLAG_BETA  1
#define FLAG_RELUA 2

// ---------------- scratch (device globals; no allocation allowed) ----------
__device__ float g_node[NN * DIM];
__device__ float g_newnode[NN * DIM];   // also reused as t-buffer
__device__ float g_agg[NN * DIM];
__device__ float g_atom[NN * HID];
__device__ float g_res[NN * HID];
__device__ float g_table[3 * TABLE_N * DIM];
__device__ float g_gsum[NG * HID];
__device__ float g_gcnt[NG];
__device__ float g_gmean[NG * HID];

// ---------------- activations ---------------------------------------------
__device__ __forceinline__ float softplusf(float x) {
    return fmaxf(x, 0.0f) + log1pf(expf(-fabsf(x)));
}
__device__ __forceinline__ float sp2f(float x) {       // 2*softplus(0.5x)
    return 2.0f * softplusf(0.5f * x);
}
__device__ __forceinline__ float sspf(float x) {       // softplus(x) - ln2
    return softplusf(x) - 0.69314718055994531f;
}

// ---------------- f32x2 packed math ----------------------------------------
__device__ __forceinline__ uint64_t pack2(float lo, float hi) {
    uint64_t r;
    asm("mov.b64 %0, {%1, %2};" : "=l"(r) : "f"(lo), "f"(hi));
    return r;
}
__device__ __forceinline__ uint64_t dup2(float v) {
    uint64_t r;
    asm("mov.b64 %0, {%1, %1};" : "=l"(r) : "f"(v));
    return r;
}
__device__ __forceinline__ void ffma2(uint64_t& d, uint64_t a, uint64_t b) {
    asm("fma.rn.f32x2 %0, %1, %2, %0;" : "+l"(d) : "l"(a), "l"(b));
}
__device__ __forceinline__ void unpack2(uint64_t v, float& lo, float& hi) {
    asm("mov.b64 {%0, %1}, %2;" : "=f"(lo), "=f"(hi) : "l"(v));
}

// ---------------- tiny utility kernels -------------------------------------
__global__ void zero_kernel(float* __restrict__ p, int n) {
    int i = blockIdx.x * blockDim.x + threadIdx.x;
    if (i < n) p[i] = 0.0f;
}

__global__ void embed_kernel(const int* __restrict__ types,
                             const float* __restrict__ emb,
                             float* __restrict__ node) {
    int i = blockIdx.x * blockDim.x + threadIdx.x;
    if (i >= NN * DIM) return;
    int n = i >> 6;      // /64
    int c = i & 63;
    node[i] = emb[types[n] * DIM + c];
}

// eh(d) table per layer: sp2(sp2(rbf(d)@cf1 + b1)@cf2 + b2)
__global__ void build_table_kernel(const float* __restrict__ cf1_w,  // [3,5,64]
                                   const float* __restrict__ cf1_b,  // [3,64]
                                   const float* __restrict__ cf2_w,  // [3,64,64]
                                   const float* __restrict__ cf2_b,  // [3,64]
                                   float* __restrict__ table) {
    __shared__ float h[DIM];
    int b = blockIdx.x;
    int layer = b / TABLE_N;
    int ent   = b % TABLE_N;
    int j = threadIdx.x;

    const float gap = CUTOFF / 4.0f;                 // linspace(0,5,5) gap = 1.25
    float d = (float)ent * (CUTOFF / (float)(TABLE_N - 1));

    float rbf[5];
#pragma unroll
    for (int r = 0; r < 5; r++) {
        float t = d - (float)r * gap;
        rbf[r] = expf(-(1.0f / gap) * t * t);
    }
    float acc = cf1_b[layer * DIM + j];
#pragma unroll
    for (int r = 0; r < 5; r++)
        acc += rbf[r] * cf1_w[(layer * 5 + r) * DIM + j];
    h[j] = sp2f(acc);
    __syncthreads();

    float acc2 = cf2_b[layer * DIM + j];
    const float* W = cf2_w + layer * DIM * DIM;
#pragma unroll 8
    for (int k = 0; k < DIM; k++)
        acc2 += h[k] * W[k * DIM + j];
    table[(layer * TABLE_N + ent) * DIM + j] = sp2f(acc2);
}

// 16 lanes per edge; each lane handles 4 consecutive floats (float4, 128-bit)
__global__ void edge_kernel(const int* __restrict__ src,
                            const int* __restrict__ dst,
                            const float* __restrict__ dist,
                            const float* __restrict__ newnode,
                            const float* __restrict__ table,   // [TABLE_N,64]
                            float* __restrict__ agg) {
    int idx = blockIdx.x * blockDim.x + threadIdx.x;
    int e = idx >> 4;
    if (e >= NE) return;
    int lane = idx & 15;

    int s = __ldg(src + e);
    int t = __ldg(dst + e);
    float dd = __ldg(dist + e);

    float f = dd * ((float)(TABLE_N - 1) / CUTOFF);
    f = fminf(fmaxf(f, 0.0f), (float)(TABLE_N - 1));
    int i0 = (int)f;
    if (i0 > TABLE_N - 2) i0 = TABLE_N - 2;
    float fr = f - (float)i0;

    const float4* nn = (const float4*)(newnode + (size_t)s * DIM);
    const float4* tb = (const float4*)(table + (size_t)i0 * DIM);

    float4 a  = nn[lane];
    float4 u0 = tb[lane];          // row i0
    float4 u1 = tb[lane + 16];     // row i0+1 (adjacent, +64 floats)

    float m0 = a.x * fmaf(fr, u1.x - u0.x, u0.x);
    float m1 = a.y * fmaf(fr, u1.y - u0.y, u0.y);
    float m2 = a.z * fmaf(fr, u1.z - u0.z, u0.z);
    float m3 = a.w * fmaf(fr, u1.w - u0.w, u0.w);

    float* out = agg + (size_t)t * DIM + lane * 4;
    asm volatile("red.global.add.v4.f32 [%0], {%1, %2, %3, %4};"
                 :: "l"(out), "f"(m0), "f"(m1), "f"(m2), "f"(m3) : "memory");
}

// graph pooling: accumulate res rows into per-graph sums
__global__ void pool_kernel(const int* __restrict__ gid,
                            const float* __restrict__ res,
                            float* __restrict__ gsum) {
    int idx = blockIdx.x * blockDim.x + threadIdx.x;   // NN * 128 threads
    if (idx >= NN * (HID / 2)) return;
    int n  = idx >> 7;        // /128
    int c2 = idx & 127;
    int g = __ldg(gid + n);
    const float2 v = ((const float2*)(res + (size_t)n * HID))[c2];
    float* out = gsum + (size_t)g * HID + c2 * 2;
    asm volatile("red.global.add.v2.f32 [%0], {%1, %2};"
                 :: "l"(out), "f"(v.x), "f"(v.y) : "memory");
}

__global__ void count_kernel(const int* __restrict__ gid, float* __restrict__ gcnt) {
    int i = blockIdx.x * blockDim.x + threadIdx.x;
    if (i < NN) atomicAdd(&gcnt[gid[i]], 1.0f);
}

__global__ void mean_kernel(const float* __restrict__ gsum,
                            const float* __restrict__ gcnt,
                            float* __restrict__ gmean) {
    int i = blockIdx.x * blockDim.x + threadIdx.x;
    if (i >= NG * HID) return;
    int g = i >> 8;   // /256
    gmean[i] = gsum[i] / fmaxf(gcnt[g], 1.0f);
}

// ---------------- SGEMM: f32x2, dup-B smem, 8x8 microtile -------------------
// C = act(A@B + bias) [+C].  A:[M,K] rm, B:[K,N] rm.  K % 32 == 0.
// BM=256, BN=64, KC=32, 256 threads. Thread (tr=tid>>3, tc=tid&7):
//   rows row0 = tr*8 .. +7 (4 f32x2 row-pairs), cols (c>>1)*16 + tc*2 + (c&1).
// Inner loop: 2 LDS.128 (A, 8-way bcast) + 4 LDS.128 (dup'd B) + 32 FFMA2.
#define BM 256
#define BN 64
#define KC 32
#define AP (BM + 4)     // padded As row stride (float4-aligned, halves STS conflicts)

__global__ __launch_bounds__(256)
void sgemm_kernel(const float* __restrict__ A,
                  const float* __restrict__ B,
                  const float* __restrict__ bias,
                  float* __restrict__ C,
                  int M, int N, int K, int act, int flags) {
    __shared__ float As[KC][AP];        // ~33 KB, k-major (transposed)
    __shared__ float Bd[KC][BN * 2];    // 16 KB, duplicated: Bd[k][2n]=Bd[k][2n+1]=B[k][n]

    int bm = blockIdx.y * BM;
    int bn = blockIdx.x * BN;
    int tid = threadIdx.x;
    int tr = tid >> 3;             // 0..31
    int tc = tid & 7;              // 0..7
    int row0 = tr * 8;

    uint64_t acc[4][8];            // [row-pair][col]
#pragma unroll
    for (int i = 0; i < 4; i++)
#pragma unroll
        for (int j = 0; j < 8; j++) acc[i][j] = 0ull;

    const bool reluA = (flags & FLAG_RELUA) != 0;

    for (int k0 = 0; k0 < K; k0 += KC) {
        // ---- load A chunk (BM x KC = 8192 floats): 8 float4 per thread ----
        // lin = q*256 + tid: m = q*32 + (tid>>3), ks = (tid&7)*4  (coalesced 128B)
#pragma unroll
        for (int q = 0; q < 8; q++) {
            int m  = q * 32 + (tid >> 3);
            int ks = (tid & 7) * 4;
            int gr = bm + m;
            float4 v = make_float4(0.f, 0.f, 0.f, 0.f);
            if (gr < M)
                v = *(const float4*)(A + (size_t)gr * K + k0 + ks);
            if (reluA) {
                v.x = fmaxf(v.x, 0.f); v.y = fmaxf(v.y, 0.f);
                v.z = fmaxf(v.z, 0.f); v.w = fmaxf(v.w, 0.f);
            }
            As[ks + 0][m] = v.x;
            As[ks + 1][m] = v.y;
            As[ks + 2][m] = v.z;
            As[ks + 3][m] = v.w;
        }
        // ---- load B chunk duplicated (KC x BN src): 8 floats per thread ----
        {
            int kk = tid >> 3;              // 0..31
            int n0 = (tid & 7) * 8;         // 0,8,...,56
            const float* Brow = B + (size_t)(k0 + kk) * N + bn;
#pragma unroll
            for (int p = 0; p < 4; p++) {
                int n = n0 + p * 2;
                float x = 0.f, y = 0.f;
                int gc = bn + n;
                if (gc + 1 < N) {
                    float2 v2 = *(const float2*)(Brow + n);
                    x = v2.x; y = v2.y;
                } else {
                    if (gc < N) x = Brow[n];
                }
                *(uint64_t*)&Bd[kk][2 * n]     = dup2(x);
                *(uint64_t*)&Bd[kk][2 * n + 2] = dup2(y);
            }
        }
        __syncthreads();

#pragma unroll
        for (int kk = 0; kk < KC; kk++) {
            float4 a0 = *(const float4*)&As[kk][row0];
            float4 a1 = *(const float4*)&As[kk][row0 + 4];
            uint64_t ap0 = pack2(a0.x, a0.y);
            uint64_t ap1 = pack2(a0.z, a0.w);
            uint64_t ap2 = pack2(a1.x, a1.y);
            uint64_t ap3 = pack2(a1.z, a1.w);
            uint64_t b[8];
#pragma unroll
            for (int j = 0; j < 4; j++) {
                float4 bv = *(const float4*)&Bd[kk][j * 32 + tc * 4];
                b[j * 2]     = pack2(bv.x, bv.y);
                b[j * 2 + 1] = pack2(bv.z, bv.w);
            }
#pragma unroll
            for (int c = 0; c < 8; c++) {
                ffma2(acc[0][c], ap0, b[c]);
                ffma2(acc[1][c], ap1, b[c]);
                ffma2(acc[2][c], ap2, b[c]);
                ffma2(acc[3][c], ap3, b[c]);
            }
        }
        __syncthreads();
    }

    // ---- epilogue: 8 rows x 8 cols ----
#pragma unroll
    for (int rp = 0; rp < 4; rp++) {
#pragma unroll
        for (int h = 0; h < 2; h++) {
            int r = bm + row0 + rp * 2 + h;
            if (r >= M) continue;
            float vals[8];
#pragma unroll
            for (int c = 0; c < 8; c++) {
                float lo, hi;
                unpack2(acc[rp][c], lo, hi);
                vals[c] = h ? hi : lo;
            }
#pragma unroll
            for (int j = 0; j < 4; j++) {
                int c0 = bn + j * 16 + tc * 2;
#pragma unroll
                for (int u = 0; u < 2; u++) {
                    int c = c0 + u;
                    if (c >= N) continue;
                    float v = vals[j * 2 + u];
                    if (bias) v += bias[c];
                    if (act == 1) v = sp2f(v);
                    else if (act == 2) v = sspf(v);
                    if (flags & FLAG_BETA) v += C[(size_t)r * N + c];
                    C[(size_t)r * N + c] = v;
                }
            }
        }
    }
}

// ---------------- driver ----------------------------------------------------
static inline dim3 gemm_grid(int M, int N) {
    return dim3((N + BN - 1) / BN, (M + BM - 1) / BM);
}

extern "C" void kernel_launch(void* const* d_in, const int* in_sizes, int n_in,
                              void* d_out, int out_size) {
    const int*   node_types = (const int*)  d_in[0];
    const int*   edge_src   = (const int*)  d_in[1];
    const int*   edge_dst   = (const int*)  d_in[2];
    const int*   graph_ids  = (const int*)  d_in[3];
    const float* distance   = (const float*)d_in[4];
    const float* emb        = (const float*)d_in[5];
    const float* conv_w1    = (const float*)d_in[6];
    const float* cf1_w      = (const float*)d_in[7];
    const float* cf1_b      = (const float*)d_in[8];
    const float* cf2_w      = (const float*)d_in[9];
    const float* cf2_b      = (const float*)d_in[10];
    const float* nl2_w      = (const float*)d_in[11];
    const float* nl2_b      = (const float*)d_in[12];
    const float* nl3_w      = (const float*)d_in[13];
    const float* nl3_b      = (const float*)d_in[14];
    const float* d1_w       = (const float*)d_in[15];
    const float* d1_b       = (const float*)d_in[16];
    const float* d2_w       = (const float*)d_in[17];
    const float* d2_b       = (const float*)d_in[18];
    const float* cls_w      = (const float*)d_in[19];
    const float* cls_b      = (const float*)d_in[20];
    const float* ac_w       = (const float*)d_in[21];
    const float* ac_b       = (const float*)d_in[22];
    float* out = (float*)d_out;

    float *node, *newnode, *agg, *atom, *res, *table, *gsum, *gcnt, *gmean;
    cudaGetSymbolAddress((void**)&node,    g_node);
    cudaGetSymbolAddress((void**)&newnode, g_newnode);
    cudaGetSymbolAddress((void**)&agg,     g_agg);
    cudaGetSymbolAddress((void**)&atom,    g_atom);
    cudaGetSymbolAddress((void**)&res,     g_res);
    cudaGetSymbolAddress((void**)&table,   g_table);
    cudaGetSymbolAddress((void**)&gsum,    g_gsum);
    cudaGetSymbolAddress((void**)&gcnt,    g_gcnt);
    cudaGetSymbolAddress((void**)&gmean,   g_gmean);

    // node = emb[node_types]
    embed_kernel<<<(NN * DIM + 255) / 256, 256>>>(node_types, emb, node);

    // per-layer eh(d) lookup tables
    build_table_kernel<<<3 * TABLE_N, DIM>>>(cf1_w, cf1_b, cf2_w, cf2_b, table);

    dim3 g64 = gemm_grid(NN, DIM);
    for (int l = 0; l < 3; l++) {
        // newnode = node @ w1
        sgemm_kernel<<<g64, 256>>>(node, conv_w1 + (size_t)l * DIM * DIM,
                                   nullptr, newnode, NN, DIM, DIM, 0, 0);
        // agg = 0
        zero_kernel<<<(NN * DIM + 255) / 256, 256>>>(agg, NN * DIM);
        // agg[dst] += newnode[src] * eh(d)
        edge_kernel<<<(NE * 16 + 255) / 256, 256>>>(
            edge_src, edge_dst, distance, newnode,
            table + (size_t)l * TABLE_N * DIM, agg);
        // t = sp2(agg @ nl2 + b2)   (reuse newnode as t)
        sgemm_kernel<<<g64, 256>>>(agg, nl2_w + (size_t)l * DIM * DIM,
                                   nl2_b + l * DIM, newnode, NN, DIM, DIM, 1, 0);
        // node += t @ nl3 + b3
        sgemm_kernel<<<g64, 256>>>(newnode, nl3_w + (size_t)l * DIM * DIM,
                                   nl3_b + l * DIM, node, NN, DIM, DIM, 0, FLAG_BETA);
    }

    // atom = ssp(node @ d1 + b)
    sgemm_kernel<<<gemm_grid(NN, HID), 256>>>(node, d1_w, d1_b, atom,
                                              NN, HID, DIM, 2, 0);
    // res = atom @ d2 + b
    sgemm_kernel<<<gemm_grid(NN, HID), 256>>>(atom, d2_w, d2_b, res,
                                              NN, HID, HID, 0, 0);
    // atoms_preds = relu(res) @ ac + b   -> out[0 : NN*100]
    sgemm_kernel<<<gemm_grid(NN, NAT), 256>>>(res, ac_w, ac_b, out,
                                              NN, NAT, HID, 0, FLAG_RELUA);

    // graph pooling
    zero_kernel<<<(NG * HID + 255) / 256, 256>>>(gsum, NG * HID);
    zero_kernel<<<(NG + 255) / 256, 256>>>(gcnt, NG);
    pool_kernel<<<(NN * (HID / 2) + 255) / 256, 256>>>(graph_ids, res, gsum);
    count_kernel<<<(NN + 255) / 256, 256>>>(graph_ids, gcnt);
    mean_kernel<<<(NG * HID + 255) / 256, 256>>>(gsum, gcnt, gmean);

    // cls_preds = gmean @ cls_w + b -> out[NN*100 : ]
    sgemm_kernel<<<gemm_grid(NG, NCLS), 256>>>(gmean, cls_w, cls_b,
                                               out + (size_t)NN * NAT,
                                               NG, NCLS, HID, 0, 0);
}